// round 3
// baseline (speedup 1.0000x reference)
#include <cuda_runtime.h>
#include <math.h>

#define NSAMP 8192
#define EPS_RE 1e-4f

// ---------------- persistent device scratch ----------------
static __device__ float g_bufA[(size_t)NSAMP * 58 * 58];
static __device__ float g_bufB[(size_t)NSAMP * 58 * 58];
static __device__ float g_part[128 * 58 * 58];
static __device__ float g_M0[58 * 58];
static __device__ float g_M0s[58 * 58];
static __device__ float g_M0is[58 * 58];
static __device__ float g_Lm[58 * 58];
static __device__ float g_Gis[58 * 58];
static __device__ float g_Ws[58 * 58];
static __device__ float g_P[58 * 58];

// ---------------- helpers ----------------
__device__ __forceinline__ float blockReduceSum(float v, float* red) {
    __syncthreads();
    int tid = threadIdx.x;
#pragma unroll
    for (int o = 16; o > 0; o >>= 1) v += __shfl_xor_sync(0xffffffffu, v, o);
    if ((tid & 31) == 0) red[tid >> 5] = v;
    __syncthreads();
    if (tid == 0) {
        float t = 0.f;
        int nw = (blockDim.x + 31) >> 5;
        for (int w = 0; w < nw; ++w) t += red[w];
        red[0] = t;
    }
    __syncthreads();
    return red[0];
}

// round-robin tournament pairing: m even, rounds r in [0, m-1), pairs k in [0, m/2)
__device__ __forceinline__ void rr_pair(int r, int k, int m, int& p, int& q) {
    int mm1 = m - 1;
    if (k == 0) { p = mm1; q = r; }
    else {
        p = r + k; if (p >= mm1) p -= mm1;
        q = r - k; if (q < 0) q += mm1;
    }
    if (p > q) { int t = p; p = q; q = t; }
}

// Parallel cyclic Jacobi eigensolver for symmetric A (n even), in shared memory.
// On exit: diag(A) = eigenvalues, columns of V = eigenvectors (A = V D V^T).
template<int n>
__device__ void jacobi_sym(float* A, float* V) {
    constexpr int ld = n + 1;
    constexpr int half = n / 2;
    __shared__ float cs[32], sn[32];
    __shared__ int s_nrot;
    const int tid = threadIdx.x, nt = blockDim.x;
    for (int i = tid; i < n * n; i += nt) {
        int r = i / n, c = i % n;
        V[r * ld + c] = (r == c) ? 1.f : 0.f;
    }
    __syncthreads();
    for (int sweep = 0; sweep < 16; ++sweep) {
        if (tid == 0) s_nrot = 0;
        __syncthreads();
        for (int r = 0; r < n - 1; ++r) {
            if (tid < half) {
                int p, q; rr_pair(r, tid, n, p, q);
                float app = A[p * ld + p], aqq = A[q * ld + q], apq = A[p * ld + q];
                float c_ = 1.f, s_ = 0.f;
                // scaled (Demmel-Veselic) threshold: keeps small eigvals relatively accurate
                float thr = 1e-13f * fabsf(app * aqq) + 1e-37f;
                if (apq * apq > thr) {
                    float tau = (aqq - app) / (2.f * apq);
                    float t = ((tau >= 0.f) ? 1.f : -1.f) / (fabsf(tau) + sqrtf(1.f + tau * tau));
                    c_ = rsqrtf(1.f + t * t);
                    s_ = t * c_;
                    atomicAdd(&s_nrot, 1);
                }
                cs[tid] = c_; sn[tid] = s_;
            }
            __syncthreads();
            // column update (A <- A J, V <- V J)
            for (int idx = tid; idx < half * n; idx += nt) {
                int k = idx / n, i = idx % n;
                float s_ = sn[k];
                if (s_ != 0.f) {
                    float c_ = cs[k];
                    int p, q; rr_pair(r, k, n, p, q);
                    float aip = A[i * ld + p], aiq = A[i * ld + q];
                    A[i * ld + p] = c_ * aip - s_ * aiq;
                    A[i * ld + q] = s_ * aip + c_ * aiq;
                    float vip = V[i * ld + p], viq = V[i * ld + q];
                    V[i * ld + p] = c_ * vip - s_ * viq;
                    V[i * ld + q] = s_ * vip + c_ * viq;
                }
            }
            __syncthreads();
            // row update (A <- J^T A)
            for (int idx = tid; idx < half * n; idx += nt) {
                int k = idx / n, j = idx % n;
                float s_ = sn[k];
                if (s_ != 0.f) {
                    float c_ = cs[k];
                    int p, q; rr_pair(r, k, n, p, q);
                    float apj = A[p * ld + j], aqj = A[q * ld + j];
                    A[p * ld + j] = c_ * apj - s_ * aqj;
                    A[q * ld + j] = s_ * apj + c_ * aqj;
                }
            }
            __syncthreads();
        }
        int nr = s_nrot;
        __syncthreads();
        if (nr == 0) break;
    }
}

// C[MxNc] = A[MxK] * B[KxNc]  (or * B^T if TB; then B is [Nc x K])
template<int M, int K, int Nc, bool TB>
__device__ __forceinline__ void matmul(const float* __restrict__ A, int lda,
                                       const float* __restrict__ B, int ldb,
                                       float* __restrict__ C, int ldc) {
    for (int idx = threadIdx.x; idx < M * Nc; idx += blockDim.x) {
        int i = idx / Nc, j = idx % Nc;
        float acc = 0.f;
#pragma unroll 4
        for (int k = 0; k < K; ++k) {
            float b = TB ? B[j * ldb + k] : B[k * ldb + j];
            acc = fmaf(A[i * lda + k], b, acc);
        }
        C[i * ldc + j] = acc;
    }
    __syncthreads();
}

// out[i][j] = sum_k V[i][k] * ls[k] * V[j][k]
template<int n, int ld>
__device__ __forceinline__ void recon_out(const float* __restrict__ V, const float* __restrict__ ls,
                                          float* __restrict__ out, int ldo) {
    for (int idx = threadIdx.x; idx < n * n; idx += blockDim.x) {
        int i = idx / n, j = idx % n;
        float acc = 0.f;
#pragma unroll 4
        for (int k = 0; k < n; ++k)
            acc = fmaf(V[i * ld + k] * ls[k], V[j * ld + k], acc);
        out[i * ldo + j] = acc;
    }
    __syncthreads();
}

template<int n, int ld>
__device__ __forceinline__ void symmetrize_sh(float* A) {
    for (int e = threadIdx.x; e < n * n; e += blockDim.x) {
        int i = e / n, j = e % n;
        if (i < j) {
            float a = A[i * ld + j], b = A[j * ld + i];
            float m = 0.5f * (a + b);
            A[i * ld + j] = m; A[j * ld + i] = m;
        }
    }
    __syncthreads();
}

// ---------------- kernels ----------------

// Y_s = W X_s W^T  (W: NOxNI, X: NIxNI)
template<int NI, int NO>
__global__ void k_bimap(const float* __restrict__ X, const float* __restrict__ W,
                        float* __restrict__ Y) {
    __shared__ float SX[NI * (NI + 1)];
    __shared__ float ST[NO * (NI + 1)];
    const int s = blockIdx.x;
    const float* Xs = X + (size_t)s * NI * NI;
    for (int e = threadIdx.x; e < NI * NI; e += blockDim.x)
        SX[(e / NI) * (NI + 1) + (e % NI)] = Xs[e];
    __syncthreads();
    matmul<NO, NI, NI, false>(W, NI, SX, NI + 1, ST, NI + 1);           // ST = W * X
    matmul<NO, NI, NO, true>(ST, NI + 1, W, NI, Y + (size_t)s * NO * NO, NO); // Y = ST * W^T
}

template<int n>
__global__ void k_psum(const float* __restrict__ X, float* __restrict__ part) {
    const int b = blockIdx.x;                 // 128 blocks
    const int per = NSAMP / 128;
    for (int e = threadIdx.x; e < n * n; e += blockDim.x) {
        float acc = 0.f;
        const float* p = X + (size_t)b * per * n * n + e;
        for (int s = 0; s < per; ++s) acc += p[(size_t)s * n * n];
        part[b * n * n + e] = acc;
    }
}

template<int n>
__global__ void k_mean_sym(const float* __restrict__ part, float* __restrict__ M, float scale) {
    __shared__ float sm[n * n];
    for (int e = threadIdx.x; e < n * n; e += blockDim.x) {
        float acc = 0.f;
        for (int b = 0; b < 128; ++b) acc += part[b * n * n + e];
        sm[e] = acc * scale;
    }
    __syncthreads();
    for (int e = threadIdx.x; e < n * n; e += blockDim.x) {
        int i = e / n, j = e % n;
        M[e] = 0.5f * (sm[e] + sm[j * n + i]);
    }
}

// eig(M) -> Ms = sqrtm(M), Mis = isqrtm(M)
template<int n>
__global__ void k_meig(const float* __restrict__ M, float* __restrict__ Ms, float* __restrict__ Mis) {
    constexpr int ld = n + 1;
    __shared__ float A[n * ld], V[n * ld], ls[n];
    for (int e = threadIdx.x; e < n * n; e += blockDim.x)
        A[(e / n) * ld + (e % n)] = M[e];
    __syncthreads();
    jacobi_sym<n>(A, V);
    for (int k = threadIdx.x; k < n; k += blockDim.x)
        ls[k] = sqrtf(fmaxf(A[k * ld + k], 1e-30f));
    __syncthreads();
    recon_out<n, ld>(V, ls, Ms, n);
    for (int k = threadIdx.x; k < n; k += blockDim.x)
        ls[k] = rsqrtf(fmaxf(A[k * ld + k], 1e-30f));
    __syncthreads();
    recon_out<n, ld>(V, ls, Mis, n);
}

// Lg_s = logm( M0is * Y_s * M0is )
template<int n>
__global__ void k_bn_log(const float* __restrict__ Y, const float* __restrict__ M0is,
                         float* __restrict__ Lg) {
    constexpr int ld = n + 1;
    __shared__ float A[n * ld], V[n * ld], T[n * ld], ls[n];
    const int s = blockIdx.x;
    const float* Ys = Y + (size_t)s * n * n;
    for (int e = threadIdx.x; e < n * n; e += blockDim.x)
        A[(e / n) * ld + (e % n)] = Ys[e];
    __syncthreads();
    matmul<n, n, n, false>(M0is, n, A, ld, T, ld);  // T = M0is * Y
    matmul<n, n, n, false>(T, ld, M0is, n, A, ld);  // A = T * M0is
    symmetrize_sh<n, ld>(A);
    jacobi_sym<n>(A, V);
    for (int k = threadIdx.x; k < n; k += blockDim.x)
        ls[k] = logf(fmaxf(A[k * ld + k], 1e-30f));
    __syncthreads();
    recon_out<n, ld>(V, ls, Lg + (size_t)s * n * n, n);
}

// block 0: E=expm(Lm); G=sym(M0s E M0s); Gis=isqrtm(G).  block 1: Ws=sqrtm(Gw).
template<int n>
__global__ void k_bn_stats(const float* __restrict__ Lm, const float* __restrict__ M0s,
                           const float* __restrict__ Gw,
                           float* __restrict__ Gis, float* __restrict__ Ws) {
    constexpr int ld = n + 1;
    __shared__ float A[n * ld], V[n * ld], T[n * ld], ls[n];
    if (blockIdx.x == 0) {
        for (int e = threadIdx.x; e < n * n; e += blockDim.x)
            A[(e / n) * ld + (e % n)] = Lm[e];
        __syncthreads();
        jacobi_sym<n>(A, V);
        for (int k = threadIdx.x; k < n; k += blockDim.x)
            ls[k] = expf(A[k * ld + k]);
        __syncthreads();
        recon_out<n, ld>(V, ls, T, ld);                 // T = expm(Lm)
        matmul<n, n, n, false>(M0s, n, T, ld, A, ld);   // A = M0s * E
        matmul<n, n, n, false>(A, ld, M0s, n, T, ld);   // T = A * M0s
        symmetrize_sh<n, ld>(T);
        jacobi_sym<n>(T, V);
        for (int k = threadIdx.x; k < n; k += blockDim.x)
            ls[k] = rsqrtf(fmaxf(T[k * ld + k], 1e-30f));
        __syncthreads();
        recon_out<n, ld>(V, ls, Gis, n);
    } else {
        for (int e = threadIdx.x; e < n * n; e += blockDim.x)
            A[(e / n) * ld + (e % n)] = Gw[e];
        __syncthreads();
        jacobi_sym<n>(A, V);
        for (int k = threadIdx.x; k < n; k += blockDim.x)
            ls[k] = sqrtf(fmaxf(A[k * ld + k], 1e-30f));
        __syncthreads();
        recon_out<n, ld>(V, ls, Ws, n);
    }
}

template<int n>
__global__ void k_pmul(const float* __restrict__ Ws, const float* __restrict__ Gis,
                       float* __restrict__ P) {
    for (int e = threadIdx.x; e < n * n; e += blockDim.x) {
        int i = e / n, j = e % n;
        float acc = 0.f;
        for (int k = 0; k < n; ++k) acc = fmaf(Ws[i * n + k], Gis[k * n + j], acc);
        P[e] = acc;
    }
}

// X_out = reeig( P Y P^T )
template<int n>
__global__ void k_bn_out(const float* __restrict__ Y, const float* __restrict__ P,
                         float* __restrict__ Xout) {
    constexpr int ld = n + 1;
    __shared__ float A[n * ld], V[n * ld], T[n * ld], ls[n];
    const int s = blockIdx.x;
    const float* Ys = Y + (size_t)s * n * n;
    for (int e = threadIdx.x; e < n * n; e += blockDim.x)
        A[(e / n) * ld + (e % n)] = Ys[e];
    __syncthreads();
    matmul<n, n, n, false>(P, n, A, ld, T, ld);  // T = P * Y
    matmul<n, n, n, true>(T, ld, P, n, A, ld);   // A = T * P^T
    symmetrize_sh<n, ld>(A);
    jacobi_sym<n>(A, V);
    for (int k = threadIdx.x; k < n; k += blockDim.x)
        ls[k] = fmaxf(A[k * ld + k], EPS_RE);
    __syncthreads();
    recon_out<n, ld>(V, ls, Xout + (size_t)s * n * n, n);
}

// feat = P Y P^T ; v = logm(feat); y = Wl @ vec(v) + bl
template<int n>
__global__ void k_final(const float* __restrict__ Y, const float* __restrict__ P,
                        const float* __restrict__ Wl, const float* __restrict__ bl,
                        float* __restrict__ feat, float* __restrict__ y) {
    constexpr int ld = n + 1;
    __shared__ float A[n * ld], V[n * ld], T[n * ld], ls[n];
    __shared__ float red[8];
    const int s = blockIdx.x;
    const float* Ys = Y + (size_t)s * n * n;
    for (int e = threadIdx.x; e < n * n; e += blockDim.x)
        A[(e / n) * ld + (e % n)] = Ys[e];
    __syncthreads();
    matmul<n, n, n, false>(P, n, A, ld, T, ld);
    matmul<n, n, n, true>(T, ld, P, n, A, ld);
    if (feat) {
        float* fs = feat + (size_t)s * n * n;
        for (int e = threadIdx.x; e < n * n; e += blockDim.x)
            fs[e] = A[(e / n) * ld + (e % n)];
    }
    symmetrize_sh<n, ld>(A);
    jacobi_sym<n>(A, V);
    for (int k = threadIdx.x; k < n; k += blockDim.x)
        ls[k] = logf(fmaxf(A[k * ld + k], 1e-30f));
    __syncthreads();
    float a0 = 0.f, a1 = 0.f;
    for (int e = threadIdx.x; e < n * n; e += blockDim.x) {
        int i = e / n, j = e % n;
        float acc = 0.f;
#pragma unroll 4
        for (int k = 0; k < n; ++k)
            acc = fmaf(V[i * ld + k] * ls[k], V[j * ld + k], acc);
        a0 = fmaf(acc, Wl[e], a0);
        a1 = fmaf(acc, Wl[n * n + e], a1);
    }
    a0 = blockReduceSum(a0, red);
    a1 = blockReduceSum(a1, red);
    if (y && threadIdx.x == 0) {
        y[s * 2 + 0] = a0 + bl[0];
        y[s * 2 + 1] = a1 + bl[1];
    }
}

// ---------------- host orchestration ----------------
template<int n>
static void run_bn(const float* Y, float* scratch, const float* Gw,
                   float* part, float* M0, float* M0s, float* M0is,
                   float* Lm, float* Gis, float* Ws, float* P) {
    k_psum<n><<<128, 256>>>(Y, part);
    k_mean_sym<n><<<1, 256>>>(part, M0, 1.0f / NSAMP);
    k_meig<n><<<1, 256>>>(M0, M0s, M0is);
    k_bn_log<n><<<NSAMP, 256>>>(Y, M0is, scratch);
    k_psum<n><<<128, 256>>>(scratch, part);
    k_mean_sym<n><<<1, 256>>>(part, Lm, 1.0f / NSAMP);
    k_bn_stats<n><<<2, 256>>>(Lm, M0s, Gw, Gis, Ws);
    k_pmul<n><<<1, 256>>>(Ws, Gis, P);
}

extern "C" void kernel_launch(void* const* d_in, const int* in_sizes, int n_in,
                              void* d_out, int out_size) {
    const float* x  = (const float*)d_in[0];
    const float* W1 = (const float*)d_in[1];
    const float* W2 = (const float*)d_in[2];
    const float* W3 = (const float*)d_in[3];
    const float* G1 = (const float*)d_in[4];
    const float* G2 = (const float*)d_in[5];
    const float* G3 = (const float*)d_in[6];
    const float* Wl = (const float*)d_in[7];
    const float* bl = (const float*)d_in[8];
    float* out = (float*)d_out;

    float *bufA, *bufB, *part, *M0, *M0s, *M0is, *Lm, *Gis, *Ws, *P;
    cudaGetSymbolAddress((void**)&bufA, g_bufA);
    cudaGetSymbolAddress((void**)&bufB, g_bufB);
    cudaGetSymbolAddress((void**)&part, g_part);
    cudaGetSymbolAddress((void**)&M0,   g_M0);
    cudaGetSymbolAddress((void**)&M0s,  g_M0s);
    cudaGetSymbolAddress((void**)&M0is, g_M0is);
    cudaGetSymbolAddress((void**)&Lm,   g_Lm);
    cudaGetSymbolAddress((void**)&Gis,  g_Gis);
    cudaGetSymbolAddress((void**)&Ws,   g_Ws);
    cudaGetSymbolAddress((void**)&P,    g_P);

    const int YE = NSAMP * 2;
    const int FE = NSAMP * 50 * 50;
    float* yout = nullptr;
    float* fout = nullptr;
    if (out_size >= YE + FE)      { yout = out; fout = out + YE; }
    else if (out_size == FE)      { fout = out; }
    else                          { yout = out; }

    // Layer 1: 62 -> 58
    k_bimap<62, 58><<<NSAMP, 256>>>(x, W1, bufA);
    run_bn<58>(bufA, bufB, G1, part, M0, M0s, M0is, Lm, Gis, Ws, P);
    k_bn_out<58><<<NSAMP, 256>>>(bufA, P, bufB);

    // Layer 2: 58 -> 54
    k_bimap<58, 54><<<NSAMP, 256>>>(bufB, W2, bufA);
    run_bn<54>(bufA, bufB, G2, part, M0, M0s, M0is, Lm, Gis, Ws, P);
    k_bn_out<54><<<NSAMP, 256>>>(bufA, P, bufB);

    // Layer 3: 54 -> 50 (no ReEig; LogEig + linear head)
    k_bimap<54, 50><<<NSAMP, 256>>>(bufB, W3, bufA);
    run_bn<50>(bufA, bufB, G3, part, M0, M0s, M0is, Lm, Gis, Ws, P);
    k_final<50><<<NSAMP, 256>>>(bufA, P, Wl, bl, fout, yout);
}

// round 5
// speedup vs baseline: 1.3167x; 1.3167x over previous
#include <cuda_runtime.h>
#include <math.h>

#define NSAMP 8192
#define EPS_RE 1e-4f

// ---------------- persistent device scratch ----------------
static __device__ float g_bufA[(size_t)NSAMP * 58 * 58];
static __device__ float g_bufB[(size_t)NSAMP * 58 * 58];
static __device__ float g_part[128 * 58 * 58];
static __device__ float g_M0[58 * 58];
static __device__ float g_M0s[58 * 58];
static __device__ float g_M0is[58 * 58];
static __device__ float g_Lm[58 * 58];
static __device__ float g_Gis[58 * 58];
static __device__ float g_Ws[58 * 58];
static __device__ float g_P[58 * 58];

// ---------------- helpers ----------------
__device__ __forceinline__ float blockReduceSum(float v, float* red) {
    __syncthreads();
    int tid = threadIdx.x;
#pragma unroll
    for (int o = 16; o > 0; o >>= 1) v += __shfl_xor_sync(0xffffffffu, v, o);
    if ((tid & 31) == 0) red[tid >> 5] = v;
    __syncthreads();
    if (tid == 0) {
        float t = 0.f;
        int nw = (blockDim.x + 31) >> 5;
        for (int w = 0; w < nw; ++w) t += red[w];
        red[0] = t;
    }
    __syncthreads();
    return red[0];
}

// round-robin tournament pairing: m even, rounds r in [0, m-1), pairs k in [0, m/2)
__device__ __forceinline__ void rr_pair(int r, int k, int m, int& p, int& q) {
    int mm1 = m - 1;
    if (k == 0) { p = mm1; q = r; }
    else {
        p = r + k; if (p >= mm1) p -= mm1;
        q = r - k; if (q < 0) q += mm1;
    }
    if (p > q) { int t = p; p = q; q = t; }
}

// Parallel cyclic Jacobi eigensolver for symmetric A (n even), in shared memory.
// On exit: diag(A) = eigenvalues, columns of V = eigenvectors (A = V D V^T).
// Pair indices precomputed per round; convergence counted via __syncthreads_count.
template<int n>
__device__ void jacobi_sym(float* __restrict__ A, float* __restrict__ V) {
    constexpr int ld = n + 1;
    constexpr int half = n / 2;
    constexpr int slots = half * 64;
    __shared__ float cs[32], sn[32];
    __shared__ int sp[32], sq[32];
    const int tid = threadIdx.x, nt = blockDim.x;
    for (int i = tid; i < n * n; i += nt) {
        int r = i / n, c = i - r * n;
        V[r * ld + c] = (r == c) ? 1.f : 0.f;
    }
    __syncthreads();
    for (int sweep = 0; sweep < 10; ++sweep) {
        int nrot = 0;
        for (int r = 0; r < n - 1; ++r) {
            bool rot = false;
            if (tid < half) {
                int p, q; rr_pair(r, tid, n, p, q);
                sp[tid] = p; sq[tid] = q;
                float app = A[p * ld + p], aqq = A[q * ld + q], apq = A[p * ld + q];
                float c_ = 1.f, s_ = 0.f;
                // scaled (Demmel-Veselic) threshold keeps small eigvals relatively accurate
                if (apq * apq > fmaf(1e-13f, fabsf(app * aqq), 1e-37f)) {
                    float tau = (aqq - app) / (2.f * apq);
                    float t = copysignf(1.f, tau) / (fabsf(tau) + sqrtf(fmaf(tau, tau, 1.f)));
                    c_ = rsqrtf(fmaf(t, t, 1.f));
                    s_ = t * c_;
                    rot = true;
                }
                cs[tid] = c_; sn[tid] = s_;
            }
            nrot += __syncthreads_count(rot);
            // column update (A <- A J, V <- V J)
            for (int idx = tid; idx < slots; idx += nt) {
                int k = idx >> 6, i = idx & 63;
                float s_ = sn[k];
                if (i < n && s_ != 0.f) {
                    float c_ = cs[k];
                    int p = sp[k], q = sq[k];
                    float aip = A[i * ld + p], aiq = A[i * ld + q];
                    A[i * ld + p] = fmaf(c_, aip, -s_ * aiq);
                    A[i * ld + q] = fmaf(s_, aip,  c_ * aiq);
                    float vip = V[i * ld + p], viq = V[i * ld + q];
                    V[i * ld + p] = fmaf(c_, vip, -s_ * viq);
                    V[i * ld + q] = fmaf(s_, vip,  c_ * viq);
                }
            }
            __syncthreads();
            // row update (A <- J^T A)
            for (int idx = tid; idx < slots; idx += nt) {
                int k = idx >> 6, j = idx & 63;
                float s_ = sn[k];
                if (j < n && s_ != 0.f) {
                    float c_ = cs[k];
                    int p = sp[k], q = sq[k];
                    float apj = A[p * ld + j], aqj = A[q * ld + j];
                    A[p * ld + j] = fmaf(c_, apj, -s_ * aqj);
                    A[q * ld + j] = fmaf(s_, apj,  c_ * aqj);
                }
            }
            __syncthreads();
        }
        if (nrot == 0) break;
    }
}

// C[MxNc] = A[MxK] * B[KxNc]  (or * B^T if TB; then B is [Nc x K]); 2x2 register tiles.
// M and Nc must be even.
template<int M, int K, int Nc, bool TB>
__device__ __forceinline__ void matmul2(const float* __restrict__ A, int lda,
                                        const float* __restrict__ B, int ldb,
                                        float* __restrict__ C, int ldc) {
    constexpr int MT = M / 2, NT = Nc / 2;
    for (int idx = threadIdx.x; idx < MT * NT; idx += blockDim.x) {
        int ti = idx / NT, tj = idx - ti * NT;
        int i = 2 * ti, j = 2 * tj;
        float a00 = 0.f, a01 = 0.f, a10 = 0.f, a11 = 0.f;
#pragma unroll 2
        for (int k = 0; k < K; ++k) {
            float x0 = A[i * lda + k], x1 = A[(i + 1) * lda + k];
            float b0 = TB ? B[j * ldb + k]       : B[k * ldb + j];
            float b1 = TB ? B[(j + 1) * ldb + k] : B[k * ldb + j + 1];
            a00 = fmaf(x0, b0, a00); a01 = fmaf(x0, b1, a01);
            a10 = fmaf(x1, b0, a10); a11 = fmaf(x1, b1, a11);
        }
        C[i * ldc + j] = a00;         C[i * ldc + j + 1] = a01;
        C[(i + 1) * ldc + j] = a10;   C[(i + 1) * ldc + j + 1] = a11;
    }
    __syncthreads();
}

// out[i][j] = sum_k V[i][k] * ls[k] * V[j][k]; 2x2 register tiles (n even).
template<int n, int ld>
__device__ __forceinline__ void recon2(const float* __restrict__ V, const float* __restrict__ ls,
                                       float* __restrict__ out, int ldo) {
    constexpr int T = n / 2;
    for (int idx = threadIdx.x; idx < T * T; idx += blockDim.x) {
        int ti = idx / T, tj = idx - ti * T;
        int i = 2 * ti, j = 2 * tj;
        float a00 = 0.f, a01 = 0.f, a10 = 0.f, a11 = 0.f;
#pragma unroll 2
        for (int k = 0; k < n; ++k) {
            float l = ls[k];
            float vi0 = V[i * ld + k] * l, vi1 = V[(i + 1) * ld + k] * l;
            float vj0 = V[j * ld + k],     vj1 = V[(j + 1) * ld + k];
            a00 = fmaf(vi0, vj0, a00); a01 = fmaf(vi0, vj1, a01);
            a10 = fmaf(vi1, vj0, a10); a11 = fmaf(vi1, vj1, a11);
        }
        out[i * ldo + j] = a00;         out[i * ldo + j + 1] = a01;
        out[(i + 1) * ldo + j] = a10;   out[(i + 1) * ldo + j + 1] = a11;
    }
    __syncthreads();
}

template<int n, int ld>
__device__ __forceinline__ void symmetrize_sh(float* A) {
    for (int e = threadIdx.x; e < n * n; e += blockDim.x) {
        int i = e / n, j = e - (e / n) * n;
        if (i < j) {
            float a = A[i * ld + j], b = A[j * ld + i];
            float m = 0.5f * (a + b);
            A[i * ld + j] = m; A[j * ld + i] = m;
        }
    }
    __syncthreads();
}

// ---------------- kernels ----------------

// Y_s = W X_s W^T  (W: NOxNI, X: NIxNI)
template<int NI, int NO>
__global__ void k_bimap(const float* __restrict__ X, const float* __restrict__ W,
                        float* __restrict__ Y) {
    __shared__ float SX[NI * (NI + 1)];
    __shared__ float ST[NO * (NI + 1)];
    const int s = blockIdx.x;
    const float* Xs = X + (size_t)s * NI * NI;
    for (int e = threadIdx.x; e < NI * NI; e += blockDim.x)
        SX[(e / NI) * (NI + 1) + (e - (e / NI) * NI)] = Xs[e];
    __syncthreads();
    matmul2<NO, NI, NI, false>(W, NI, SX, NI + 1, ST, NI + 1);                 // ST = W * X
    matmul2<NO, NI, NO, true>(ST, NI + 1, W, NI, Y + (size_t)s * NO * NO, NO); // Y = ST * W^T
}

template<int n>
__global__ void k_psum(const float* __restrict__ X, float* __restrict__ part) {
    const int b = blockIdx.x;                 // 128 blocks
    const int per = NSAMP / 128;
    for (int e = threadIdx.x; e < n * n; e += blockDim.x) {
        float acc = 0.f;
        const float* p = X + (size_t)b * per * n * n + e;
        for (int s = 0; s < per; ++s) acc += p[(size_t)s * n * n];
        part[b * n * n + e] = acc;
    }
}

template<int n>
__global__ void k_mean_sym(const float* __restrict__ part, float* __restrict__ M, float scale) {
    __shared__ float sm[n * n];
    for (int e = threadIdx.x; e < n * n; e += blockDim.x) {
        float acc = 0.f;
        for (int b = 0; b < 128; ++b) acc += part[b * n * n + e];
        sm[e] = acc * scale;
    }
    __syncthreads();
    for (int e = threadIdx.x; e < n * n; e += blockDim.x) {
        int i = e / n, j = e - (e / n) * n;
        M[e] = 0.5f * (sm[e] + sm[j * n + i]);
    }
}

// eig(M) -> Ms = sqrtm(M), Mis = isqrtm(M)
template<int n>
__global__ void k_meig(const float* __restrict__ M, float* __restrict__ Ms, float* __restrict__ Mis) {
    constexpr int ld = n + 1;
    __shared__ float A[n * ld], V[n * ld], ls[n];
    for (int e = threadIdx.x; e < n * n; e += blockDim.x)
        A[(e / n) * ld + (e - (e / n) * n)] = M[e];
    __syncthreads();
    jacobi_sym<n>(A, V);
    for (int k = threadIdx.x; k < n; k += blockDim.x)
        ls[k] = sqrtf(fmaxf(A[k * ld + k], 1e-30f));
    __syncthreads();
    recon2<n, ld>(V, ls, Ms, n);
    for (int k = threadIdx.x; k < n; k += blockDim.x)
        ls[k] = rsqrtf(fmaxf(A[k * ld + k], 1e-30f));
    __syncthreads();
    recon2<n, ld>(V, ls, Mis, n);
}

// Lg_s = logm( M0is * Y_s * M0is )   (T aliased onto V)
template<int n>
__global__ void k_bn_log(const float* __restrict__ Y, const float* __restrict__ M0is,
                         float* __restrict__ Lg) {
    constexpr int ld = n + 1;
    __shared__ float A[n * ld], V[n * ld], ls[n];
    const int s = blockIdx.x;
    const float* Ys = Y + (size_t)s * n * n;
    for (int e = threadIdx.x; e < n * n; e += blockDim.x)
        A[(e / n) * ld + (e - (e / n) * n)] = Ys[e];
    __syncthreads();
    matmul2<n, n, n, false>(M0is, n, A, ld, V, ld);  // V = M0is * Y
    matmul2<n, n, n, false>(V, ld, M0is, n, A, ld);  // A = V * M0is
    symmetrize_sh<n, ld>(A);
    jacobi_sym<n>(A, V);
    for (int k = threadIdx.x; k < n; k += blockDim.x)
        ls[k] = logf(fmaxf(A[k * ld + k], 1e-30f));
    __syncthreads();
    recon2<n, ld>(V, ls, Lg + (size_t)s * n * n, n);
}

// block 0: E=expm(Lm); G=sym(M0s E M0s); Gis=isqrtm(G).  block 1: Ws=sqrtm(Gw).
template<int n>
__global__ void k_bn_stats(const float* __restrict__ Lm, const float* __restrict__ M0s,
                           const float* __restrict__ Gw,
                           float* __restrict__ Gis, float* __restrict__ Ws) {
    constexpr int ld = n + 1;
    __shared__ float A[n * ld], V[n * ld], ls[n];
    if (blockIdx.x == 0) {
        for (int e = threadIdx.x; e < n * n; e += blockDim.x)
            A[(e / n) * ld + (e - (e / n) * n)] = Lm[e];
        __syncthreads();
        jacobi_sym<n>(A, V);
        for (int k = threadIdx.x; k < n; k += blockDim.x)
            ls[k] = expf(A[k * ld + k]);
        __syncthreads();
        recon2<n, ld>(V, ls, A, ld);                   // A = expm(Lm)   (reads only V, ls)
        matmul2<n, n, n, false>(M0s, n, A, ld, V, ld); // V = M0s * E
        matmul2<n, n, n, false>(V, ld, M0s, n, A, ld); // A = V * M0s
        symmetrize_sh<n, ld>(A);
        jacobi_sym<n>(A, V);
        for (int k = threadIdx.x; k < n; k += blockDim.x)
            ls[k] = rsqrtf(fmaxf(A[k * ld + k], 1e-30f));
        __syncthreads();
        recon2<n, ld>(V, ls, Gis, n);
    } else {
        for (int e = threadIdx.x; e < n * n; e += blockDim.x)
            A[(e / n) * ld + (e - (e / n) * n)] = Gw[e];
        __syncthreads();
        jacobi_sym<n>(A, V);
        for (int k = threadIdx.x; k < n; k += blockDim.x)
            ls[k] = sqrtf(fmaxf(A[k * ld + k], 1e-30f));
        __syncthreads();
        recon2<n, ld>(V, ls, Ws, n);
    }
}

template<int n>
__global__ void k_pmul(const float* __restrict__ Ws, const float* __restrict__ Gis,
                       float* __restrict__ P) {
    for (int e = threadIdx.x; e < n * n; e += blockDim.x) {
        int i = e / n, j = e - (e / n) * n;
        float acc = 0.f;
        for (int k = 0; k < n; ++k) acc = fmaf(Ws[i * n + k], Gis[k * n + j], acc);
        P[e] = acc;
    }
}

// X_out = reeig( P Y P^T )
template<int n>
__global__ void k_bn_out(const float* __restrict__ Y, const float* __restrict__ P,
                         float* __restrict__ Xout) {
    constexpr int ld = n + 1;
    __shared__ float A[n * ld], V[n * ld], ls[n];
    const int s = blockIdx.x;
    const float* Ys = Y + (size_t)s * n * n;
    for (int e = threadIdx.x; e < n * n; e += blockDim.x)
        A[(e / n) * ld + (e - (e / n) * n)] = Ys[e];
    __syncthreads();
    matmul2<n, n, n, false>(P, n, A, ld, V, ld);  // V = P * Y
    matmul2<n, n, n, true>(V, ld, P, n, A, ld);   // A = V * P^T
    symmetrize_sh<n, ld>(A);
    jacobi_sym<n>(A, V);
    for (int k = threadIdx.x; k < n; k += blockDim.x)
        ls[k] = fmaxf(A[k * ld + k], EPS_RE);
    __syncthreads();
    recon2<n, ld>(V, ls, Xout + (size_t)s * n * n, n);
}

// feat = P Y P^T ; v = logm(feat); y = Wl @ vec(v) + bl
template<int n>
__global__ void k_final(const float* __restrict__ Y, const float* __restrict__ P,
                        const float* __restrict__ Wl, const float* __restrict__ bl,
                        float* __restrict__ feat, float* __restrict__ y) {
    constexpr int ld = n + 1;
    constexpr int T = n / 2;
    __shared__ float A[n * ld], V[n * ld], ls[n];
    __shared__ float red[8];
    const int s = blockIdx.x;
    const float* Ys = Y + (size_t)s * n * n;
    for (int e = threadIdx.x; e < n * n; e += blockDim.x)
        A[(e / n) * ld + (e - (e / n) * n)] = Ys[e];
    __syncthreads();
    matmul2<n, n, n, false>(P, n, A, ld, V, ld);
    matmul2<n, n, n, true>(V, ld, P, n, A, ld);
    if (feat) {
        float* fs = feat + (size_t)s * n * n;
        for (int e = threadIdx.x; e < n * n; e += blockDim.x)
            fs[e] = A[(e / n) * ld + (e - (e / n) * n)];
        __syncthreads();
    }
    symmetrize_sh<n, ld>(A);
    jacobi_sym<n>(A, V);
    for (int k = threadIdx.x; k < n; k += blockDim.x)
        ls[k] = logf(fmaxf(A[k * ld + k], 1e-30f));
    __syncthreads();
    float a0 = 0.f, a1 = 0.f;
    for (int idx = threadIdx.x; idx < T * T; idx += blockDim.x) {
        int ti = idx / T, tj = idx - ti * T;
        int i = 2 * ti, j = 2 * tj;
        float a00 = 0.f, a01 = 0.f, a10 = 0.f, a11 = 0.f;
#pragma unroll 2
        for (int k = 0; k < n; ++k) {
            float l = ls[k];
            float vi0 = V[i * ld + k] * l, vi1 = V[(i + 1) * ld + k] * l;
            float vj0 = V[j * ld + k],     vj1 = V[(j + 1) * ld + k];
            a00 = fmaf(vi0, vj0, a00); a01 = fmaf(vi0, vj1, a01);
            a10 = fmaf(vi1, vj0, a10); a11 = fmaf(vi1, vj1, a11);
        }
        int e00 = i * n + j, e01 = i * n + j + 1, e10 = (i + 1) * n + j, e11 = (i + 1) * n + j + 1;
        a0 = fmaf(a00, Wl[e00], a0); a0 = fmaf(a01, Wl[e01], a0);
        a0 = fmaf(a10, Wl[e10], a0); a0 = fmaf(a11, Wl[e11], a0);
        a1 = fmaf(a00, Wl[n * n + e00], a1); a1 = fmaf(a01, Wl[n * n + e01], a1);
        a1 = fmaf(a10, Wl[n * n + e10], a1); a1 = fmaf(a11, Wl[n * n + e11], a1);
    }
    a0 = blockReduceSum(a0, red);
    a1 = blockReduceSum(a1, red);
    if (y && threadIdx.x == 0) {
        y[s * 2 + 0] = a0 + bl[0];
        y[s * 2 + 1] = a1 + bl[1];
    }
}

// ---------------- host orchestration ----------------
template<int n>
static void run_bn(const float* Y, float* scratch, const float* Gw,
                   float* part, float* M0, float* M0s, float* M0is,
                   float* Lm, float* Gis, float* Ws, float* P) {
    k_psum<n><<<128, 256>>>(Y, part);
    k_mean_sym<n><<<1, 1024>>>(part, M0, 1.0f / NSAMP);
    k_meig<n><<<1, 1024>>>(M0, M0s, M0is);
    k_bn_log<n><<<NSAMP, 256>>>(Y, M0is, scratch);
    k_psum<n><<<128, 256>>>(scratch, part);
    k_mean_sym<n><<<1, 1024>>>(part, Lm, 1.0f / NSAMP);
    k_bn_stats<n><<<2, 1024>>>(Lm, M0s, Gw, Gis, Ws);
    k_pmul<n><<<1, 256>>>(Ws, Gis, P);
}

extern "C" void kernel_launch(void* const* d_in, const int* in_sizes, int n_in,
                              void* d_out, int out_size) {
    const float* x  = (const float*)d_in[0];
    const float* W1 = (const float*)d_in[1];
    const float* W2 = (const float*)d_in[2];
    const float* W3 = (const float*)d_in[3];
    const float* G1 = (const float*)d_in[4];
    const float* G2 = (const float*)d_in[5];
    const float* G3 = (const float*)d_in[6];
    const float* Wl = (const float*)d_in[7];
    const float* bl = (const float*)d_in[8];
    float* out = (float*)d_out;

    float *bufA, *bufB, *part, *M0, *M0s, *M0is, *Lm, *Gis, *Ws, *P;
    cudaGetSymbolAddress((void**)&bufA, g_bufA);
    cudaGetSymbolAddress((void**)&bufB, g_bufB);
    cudaGetSymbolAddress((void**)&part, g_part);
    cudaGetSymbolAddress((void**)&M0,   g_M0);
    cudaGetSymbolAddress((void**)&M0s,  g_M0s);
    cudaGetSymbolAddress((void**)&M0is, g_M0is);
    cudaGetSymbolAddress((void**)&Lm,   g_Lm);
    cudaGetSymbolAddress((void**)&Gis,  g_Gis);
    cudaGetSymbolAddress((void**)&Ws,   g_Ws);
    cudaGetSymbolAddress((void**)&P,    g_P);

    const int YE = NSAMP * 2;
    const int FE = NSAMP * 50 * 50;
    float* yout = nullptr;
    float* fout = nullptr;
    if (out_size >= YE + FE)      { yout = out; fout = out + YE; }
    else if (out_size == FE)      { fout = out; }
    else                          { yout = out; }

    // Layer 1: 62 -> 58
    k_bimap<62, 58><<<NSAMP, 256>>>(x, W1, bufA);
    run_bn<58>(bufA, bufB, G1, part, M0, M0s, M0is, Lm, Gis, Ws, P);
    k_bn_out<58><<<NSAMP, 256>>>(bufA, P, bufB);

    // Layer 2: 58 -> 54
    k_bimap<58, 54><<<NSAMP, 256>>>(bufB, W2, bufA);
    run_bn<54>(bufA, bufB, G2, part, M0, M0s, M0is, Lm, Gis, Ws, P);
    k_bn_out<54><<<NSAMP, 256>>>(bufA, P, bufB);

    // Layer 3: 54 -> 50 (no ReEig; LogEig + linear head)
    k_bimap<54, 50><<<NSAMP, 256>>>(bufB, W3, bufA);
    run_bn<50>(bufA, bufB, G3, part, M0, M0s, M0is, Lm, Gis, Ws, P);
    k_final<50><<<NSAMP, 256>>>(bufA, P, Wl, bl, fout, yout);
}

// round 7
// speedup vs baseline: 1.3778x; 1.0464x over previous
#include <cuda_runtime.h>
#include <math.h>

#define NSAMP 8192
#define EPS_RE 1e-4f

// ---------------- persistent device scratch ----------------
static __device__ float g_bufA[(size_t)NSAMP * 58 * 58];
static __device__ float g_bufB[(size_t)NSAMP * 58 * 58];
static __device__ float g_part[128 * 58 * 58];
static __device__ float g_M0[58 * 58];
static __device__ float g_M0s[58 * 58];
static __device__ float g_M0is[58 * 58];
static __device__ float g_Lm[58 * 58];
static __device__ float g_Gis[58 * 58];
static __device__ float g_Ws[58 * 58];
static __device__ float g_P[58 * 58];

// ---------------- helpers ----------------
__device__ __forceinline__ float blockReduceSum(float v, float* red) {
    __syncthreads();
    int tid = threadIdx.x;
#pragma unroll
    for (int o = 16; o > 0; o >>= 1) v += __shfl_xor_sync(0xffffffffu, v, o);
    if ((tid & 31) == 0) red[tid >> 5] = v;
    __syncthreads();
    if (tid == 0) {
        float t = 0.f;
        int nw = (blockDim.x + 31) >> 5;
        for (int w = 0; w < nw; ++w) t += red[w];
        red[0] = t;
    }
    __syncthreads();
    return red[0];
}

// round-robin tournament pairing: m even, rounds r in [0, m-1), pairs k in [0, m/2)
__device__ __forceinline__ void rr_pair(int r, int k, int m, int& p, int& q) {
    int mm1 = m - 1;
    if (k == 0) { p = mm1; q = r; }
    else {
        p = r + k; if (p >= mm1) p -= mm1;
        q = r - k; if (q < 0) q += mm1;
    }
    if (p > q) { int t = p; p = q; q = t; }
}

// Parallel cyclic Jacobi eigensolver for symmetric A (n even), in shared memory.
// On exit: diag(A) = eigenvalues, columns of V = eigenvectors (A = V D V^T).
// Pair indices precomputed per round; 2 rows per slot; exact slot count.
template<int n>
__device__ void jacobi_sym(float* __restrict__ A, float* __restrict__ V) {
    constexpr int ld = n + 1;
    constexpr int half = n / 2;
    constexpr int hn = n / 2;            // row-pairs per matrix column pass
    constexpr int slots = half * hn;     // exact work items (each does 2 rows)
    __shared__ float cs[32], sn[32];
    __shared__ int sp[32], sq[32];
    const int tid = threadIdx.x, nt = blockDim.x;
    for (int i = tid; i < n * n; i += nt) {
        int r = i / n, c = i - r * n;
        V[r * ld + c] = (r == c) ? 1.f : 0.f;
    }
    __syncthreads();
    for (int sweep = 0; sweep < 12; ++sweep) {
        int nrot = 0;
        for (int r = 0; r < n - 1; ++r) {
            bool rot = false;
            if (tid < half) {
                int p, q; rr_pair(r, tid, n, p, q);
                sp[tid] = p; sq[tid] = q;
                float app = A[p * ld + p], aqq = A[q * ld + q], apq = A[p * ld + q];
                float c_ = 1.f, s_ = 0.f;
                // scaled (Demmel-Veselic) threshold; loosened to 1e-10 (rel off ~1e-5)
                if (apq * apq > fmaf(1e-10f, fabsf(app * aqq), 1e-37f)) {
                    float tau = (aqq - app) / (2.f * apq);
                    float t = copysignf(1.f, tau) / (fabsf(tau) + sqrtf(fmaf(tau, tau, 1.f)));
                    c_ = rsqrtf(fmaf(t, t, 1.f));
                    s_ = t * c_;
                    rot = true;
                }
                cs[tid] = c_; sn[tid] = s_;
            }
            nrot += __syncthreads_count(rot);
            // column update (A <- A J, V <- V J); each slot handles rows 2r2, 2r2+1
            for (int idx = tid; idx < slots; idx += nt) {
                int k = idx / hn, r2 = idx - k * hn;
                float s_ = sn[k];
                if (s_ != 0.f) {
                    float c_ = cs[k];
                    int p = sp[k], q = sq[k];
                    int i0 = 2 * r2, i1 = i0 + 1;
                    float a0p = A[i0 * ld + p], a0q = A[i0 * ld + q];
                    A[i0 * ld + p] = fmaf(c_, a0p, -s_ * a0q);
                    A[i0 * ld + q] = fmaf(s_, a0p,  c_ * a0q);
                    float v0p = V[i0 * ld + p], v0q = V[i0 * ld + q];
                    V[i0 * ld + p] = fmaf(c_, v0p, -s_ * v0q);
                    V[i0 * ld + q] = fmaf(s_, v0p,  c_ * v0q);
                    float a1p = A[i1 * ld + p], a1q = A[i1 * ld + q];
                    A[i1 * ld + p] = fmaf(c_, a1p, -s_ * a1q);
                    A[i1 * ld + q] = fmaf(s_, a1p,  c_ * a1q);
                    float v1p = V[i1 * ld + p], v1q = V[i1 * ld + q];
                    V[i1 * ld + p] = fmaf(c_, v1p, -s_ * v1q);
                    V[i1 * ld + q] = fmaf(s_, v1p,  c_ * v1q);
                }
            }
            __syncthreads();
            // row update (A <- J^T A); each slot handles cols 2r2, 2r2+1
            for (int idx = tid; idx < slots; idx += nt) {
                int k = idx / hn, r2 = idx - k * hn;
                float s_ = sn[k];
                if (s_ != 0.f) {
                    float c_ = cs[k];
                    int p = sp[k], q = sq[k];
                    int j0 = 2 * r2, j1 = j0 + 1;
                    float ap0 = A[p * ld + j0], aq0 = A[q * ld + j0];
                    A[p * ld + j0] = fmaf(c_, ap0, -s_ * aq0);
                    A[q * ld + j0] = fmaf(s_, ap0,  c_ * aq0);
                    float ap1 = A[p * ld + j1], aq1 = A[q * ld + j1];
                    A[p * ld + j1] = fmaf(c_, ap1, -s_ * aq1);
                    A[q * ld + j1] = fmaf(s_, ap1,  c_ * aq1);
                }
            }
            __syncthreads();
        }
        if (nrot == 0) break;
    }
}

// C[MxNc] = A[MxK] * B[KxNc]  (or * B^T if TB; then B is [Nc x K]); 2x2 register tiles.
// M and Nc must be even.
template<int M, int K, int Nc, bool TB>
__device__ __forceinline__ void matmul2(const float* __restrict__ A, int lda,
                                        const float* __restrict__ B, int ldb,
                                        float* __restrict__ C, int ldc) {
    constexpr int MT = M / 2, NT = Nc / 2;
    for (int idx = threadIdx.x; idx < MT * NT; idx += blockDim.x) {
        int ti = idx / NT, tj = idx - ti * NT;
        int i = 2 * ti, j = 2 * tj;
        float a00 = 0.f, a01 = 0.f, a10 = 0.f, a11 = 0.f;
#pragma unroll 2
        for (int k = 0; k < K; ++k) {
            float x0 = A[i * lda + k], x1 = A[(i + 1) * lda + k];
            float b0 = TB ? B[j * ldb + k]       : B[k * ldb + j];
            float b1 = TB ? B[(j + 1) * ldb + k] : B[k * ldb + j + 1];
            a00 = fmaf(x0, b0, a00); a01 = fmaf(x0, b1, a01);
            a10 = fmaf(x1, b0, a10); a11 = fmaf(x1, b1, a11);
        }
        C[i * ldc + j] = a00;         C[i * ldc + j + 1] = a01;
        C[(i + 1) * ldc + j] = a10;   C[(i + 1) * ldc + j + 1] = a11;
    }
    __syncthreads();
}

// out[i][j] = sum_k V[i][k] * ls[k] * V[j][k]; 2x2 register tiles (n even).
template<int n, int ld>
__device__ __forceinline__ void recon2(const float* __restrict__ V, const float* __restrict__ ls,
                                       float* __restrict__ out, int ldo) {
    constexpr int T = n / 2;
    for (int idx = threadIdx.x; idx < T * T; idx += blockDim.x) {
        int ti = idx / T, tj = idx - ti * T;
        int i = 2 * ti, j = 2 * tj;
        float a00 = 0.f, a01 = 0.f, a10 = 0.f, a11 = 0.f;
#pragma unroll 2
        for (int k = 0; k < n; ++k) {
            float l = ls[k];
            float vi0 = V[i * ld + k] * l, vi1 = V[(i + 1) * ld + k] * l;
            float vj0 = V[j * ld + k],     vj1 = V[(j + 1) * ld + k];
            a00 = fmaf(vi0, vj0, a00); a01 = fmaf(vi0, vj1, a01);
            a10 = fmaf(vi1, vj0, a10); a11 = fmaf(vi1, vj1, a11);
        }
        out[i * ldo + j] = a00;         out[i * ldo + j + 1] = a01;
        out[(i + 1) * ldo + j] = a10;   out[(i + 1) * ldo + j + 1] = a11;
    }
    __syncthreads();
}

template<int n, int ld>
__device__ __forceinline__ void symmetrize_sh(float* A) {
    for (int e = threadIdx.x; e < n * n; e += blockDim.x) {
        int i = e / n, j = e - (e / n) * n;
        if (i < j) {
            float a = A[i * ld + j], b = A[j * ld + i];
            float m = 0.5f * (a + b);
            A[i * ld + j] = m; A[j * ld + i] = m;
        }
    }
    __syncthreads();
}

// ---------------- kernels ----------------

// Y_s = W X_s W^T  (W: NOxNI, X: NIxNI)
template<int NI, int NO>
__global__ void k_bimap(const float* __restrict__ X, const float* __restrict__ W,
                        float* __restrict__ Y) {
    __shared__ float SX[NI * (NI + 1)];
    __shared__ float ST[NO * (NI + 1)];
    const int s = blockIdx.x;
    const float* Xs = X + (size_t)s * NI * NI;
    for (int e = threadIdx.x; e < NI * NI; e += blockDim.x)
        SX[(e / NI) * (NI + 1) + (e - (e / NI) * NI)] = Xs[e];
    __syncthreads();
    matmul2<NO, NI, NI, false>(W, NI, SX, NI + 1, ST, NI + 1);                 // ST = W * X
    matmul2<NO, NI, NO, true>(ST, NI + 1, W, NI, Y + (size_t)s * NO * NO, NO); // Y = ST * W^T
}

template<int n>
__global__ void k_psum(const float* __restrict__ X, float* __restrict__ part) {
    const int b = blockIdx.x;                 // 128 blocks
    const int per = NSAMP / 128;
    for (int e = threadIdx.x; e < n * n; e += blockDim.x) {
        float acc = 0.f;
        const float* p = X + (size_t)b * per * n * n + e;
        for (int s = 0; s < per; ++s) acc += p[(size_t)s * n * n];
        part[b * n * n + e] = acc;
    }
}

template<int n>
__global__ void k_mean_sym(const float* __restrict__ part, float* __restrict__ M, float scale) {
    __shared__ float sm[n * n];
    for (int e = threadIdx.x; e < n * n; e += blockDim.x) {
        float acc = 0.f;
        for (int b = 0; b < 128; ++b) acc += part[b * n * n + e];
        sm[e] = acc * scale;
    }
    __syncthreads();
    for (int e = threadIdx.x; e < n * n; e += blockDim.x) {
        int i = e / n, j = e - (e / n) * n;
        M[e] = 0.5f * (sm[e] + sm[j * n + i]);
    }
}

// eig(M) -> Ms = sqrtm(M), Mis = isqrtm(M)
template<int n>
__global__ void k_meig(const float* __restrict__ M, float* __restrict__ Ms, float* __restrict__ Mis) {
    constexpr int ld = n + 1;
    __shared__ float A[n * ld], V[n * ld], ls[n];
    for (int e = threadIdx.x; e < n * n; e += blockDim.x)
        A[(e / n) * ld + (e - (e / n) * n)] = M[e];
    __syncthreads();
    jacobi_sym<n>(A, V);
    for (int k = threadIdx.x; k < n; k += blockDim.x)
        ls[k] = sqrtf(fmaxf(A[k * ld + k], 1e-30f));
    __syncthreads();
    recon2<n, ld>(V, ls, Ms, n);
    for (int k = threadIdx.x; k < n; k += blockDim.x)
        ls[k] = rsqrtf(fmaxf(A[k * ld + k], 1e-30f));
    __syncthreads();
    recon2<n, ld>(V, ls, Mis, n);
}

// Lg_s = logm( M0is * Y_s * M0is )   (T aliased onto V)
template<int n>
__global__ void k_bn_log(const float* __restrict__ Y, const float* __restrict__ M0is,
                         float* __restrict__ Lg) {
    constexpr int ld = n + 1;
    __shared__ float A[n * ld], V[n * ld], ls[n];
    const int s = blockIdx.x;
    const float* Ys = Y + (size_t)s * n * n;
    for (int e = threadIdx.x; e < n * n; e += blockDim.x)
        A[(e / n) * ld + (e - (e / n) * n)] = Ys[e];
    __syncthreads();
    matmul2<n, n, n, false>(M0is, n, A, ld, V, ld);  // V = M0is * Y
    matmul2<n, n, n, false>(V, ld, M0is, n, A, ld);  // A = V * M0is
    symmetrize_sh<n, ld>(A);
    jacobi_sym<n>(A, V);
    for (int k = threadIdx.x; k < n; k += blockDim.x)
        ls[k] = logf(fmaxf(A[k * ld + k], 1e-30f));
    __syncthreads();
    recon2<n, ld>(V, ls, Lg + (size_t)s * n * n, n);
}

// block 0: E=expm(Lm); G=sym(M0s E M0s); Gis=isqrtm(G).  block 1: Ws=sqrtm(Gw).
template<int n>
__global__ void k_bn_stats(const float* __restrict__ Lm, const float* __restrict__ M0s,
                           const float* __restrict__ Gw,
                           float* __restrict__ Gis, float* __restrict__ Ws) {
    constexpr int ld = n + 1;
    __shared__ float A[n * ld], V[n * ld], ls[n];
    if (blockIdx.x == 0) {
        for (int e = threadIdx.x; e < n * n; e += blockDim.x)
            A[(e / n) * ld + (e - (e / n) * n)] = Lm[e];
        __syncthreads();
        jacobi_sym<n>(A, V);
        for (int k = threadIdx.x; k < n; k += blockDim.x)
            ls[k] = expf(A[k * ld + k]);
        __syncthreads();
        recon2<n, ld>(V, ls, A, ld);                   // A = expm(Lm)   (reads only V, ls)
        matmul2<n, n, n, false>(M0s, n, A, ld, V, ld); // V = M0s * E
        matmul2<n, n, n, false>(V, ld, M0s, n, A, ld); // A = V * M0s
        symmetrize_sh<n, ld>(A);
        jacobi_sym<n>(A, V);
        for (int k = threadIdx.x; k < n; k += blockDim.x)
            ls[k] = rsqrtf(fmaxf(A[k * ld + k], 1e-30f));
        __syncthreads();
        recon2<n, ld>(V, ls, Gis, n);
    } else {
        for (int e = threadIdx.x; e < n * n; e += blockDim.x)
            A[(e / n) * ld + (e - (e / n) * n)] = Gw[e];
        __syncthreads();
        jacobi_sym<n>(A, V);
        for (int k = threadIdx.x; k < n; k += blockDim.x)
            ls[k] = sqrtf(fmaxf(A[k * ld + k], 1e-30f));
        __syncthreads();
        recon2<n, ld>(V, ls, Ws, n);
    }
}

template<int n>
__global__ void k_pmul(const float* __restrict__ Ws, const float* __restrict__ Gis,
                       float* __restrict__ P) {
    for (int e = threadIdx.x; e < n * n; e += blockDim.x) {
        int i = e / n, j = e - (e / n) * n;
        float acc = 0.f;
        for (int k = 0; k < n; ++k) acc = fmaf(Ws[i * n + k], Gis[k * n + j], acc);
        P[e] = acc;
    }
}

// X_out = reeig( P Y P^T )
template<int n>
__global__ void k_bn_out(const float* __restrict__ Y, const float* __restrict__ P,
                         float* __restrict__ Xout) {
    constexpr int ld = n + 1;
    __shared__ float A[n * ld], V[n * ld], ls[n];
    const int s = blockIdx.x;
    const float* Ys = Y + (size_t)s * n * n;
    for (int e = threadIdx.x; e < n * n; e += blockDim.x)
        A[(e / n) * ld + (e - (e / n) * n)] = Ys[e];
    __syncthreads();
    matmul2<n, n, n, false>(P, n, A, ld, V, ld);  // V = P * Y
    matmul2<n, n, n, true>(V, ld, P, n, A, ld);   // A = V * P^T
    symmetrize_sh<n, ld>(A);
    jacobi_sym<n>(A, V);
    for (int k = threadIdx.x; k < n; k += blockDim.x)
        ls[k] = fmaxf(A[k * ld + k], EPS_RE);
    __syncthreads();
    recon2<n, ld>(V, ls, Xout + (size_t)s * n * n, n);
}

// feat = P Y P^T ; v = logm(feat); y = Wl @ vec(v) + bl
template<int n>
__global__ void k_final(const float* __restrict__ Y, const float* __restrict__ P,
                        const float* __restrict__ Wl, const float* __restrict__ bl,
                        float* __restrict__ feat, float* __restrict__ y) {
    constexpr int ld = n + 1;
    constexpr int T = n / 2;
    __shared__ float A[n * ld], V[n * ld], ls[n];
    __shared__ float red[8];
    const int s = blockIdx.x;
    const float* Ys = Y + (size_t)s * n * n;
    for (int e = threadIdx.x; e < n * n; e += blockDim.x)
        A[(e / n) * ld + (e - (e / n) * n)] = Ys[e];
    __syncthreads();
    matmul2<n, n, n, false>(P, n, A, ld, V, ld);
    matmul2<n, n, n, true>(V, ld, P, n, A, ld);
    if (feat) {
        float* fs = feat + (size_t)s * n * n;
        for (int e = threadIdx.x; e < n * n; e += blockDim.x)
            fs[e] = A[(e / n) * ld + (e - (e / n) * n)];
        __syncthreads();
    }
    symmetrize_sh<n, ld>(A);
    jacobi_sym<n>(A, V);
    for (int k = threadIdx.x; k < n; k += blockDim.x)
        ls[k] = logf(fmaxf(A[k * ld + k], 1e-30f));
    __syncthreads();
    float a0 = 0.f, a1 = 0.f;
    for (int idx = threadIdx.x; idx < T * T; idx += blockDim.x) {
        int ti = idx / T, tj = idx - ti * T;
        int i = 2 * ti, j = 2 * tj;
        float a00 = 0.f, a01 = 0.f, a10 = 0.f, a11 = 0.f;
#pragma unroll 2
        for (int k = 0; k < n; ++k) {
            float l = ls[k];
            float vi0 = V[i * ld + k] * l, vi1 = V[(i + 1) * ld + k] * l;
            float vj0 = V[j * ld + k],     vj1 = V[(j + 1) * ld + k];
            a00 = fmaf(vi0, vj0, a00); a01 = fmaf(vi0, vj1, a01);
            a10 = fmaf(vi1, vj0, a10); a11 = fmaf(vi1, vj1, a11);
        }
        int e00 = i * n + j, e01 = i * n + j + 1, e10 = (i + 1) * n + j, e11 = (i + 1) * n + j + 1;
        a0 = fmaf(a00, Wl[e00], a0); a0 = fmaf(a01, Wl[e01], a0);
        a0 = fmaf(a10, Wl[e10], a0); a0 = fmaf(a11, Wl[e11], a0);
        a1 = fmaf(a00, Wl[n * n + e00], a1); a1 = fmaf(a01, Wl[n * n + e01], a1);
        a1 = fmaf(a10, Wl[n * n + e10], a1); a1 = fmaf(a11, Wl[n * n + e11], a1);
    }
    a0 = blockReduceSum(a0, red);
    a1 = blockReduceSum(a1, red);
    if (y && threadIdx.x == 0) {
        y[s * 2 + 0] = a0 + bl[0];
        y[s * 2 + 1] = a1 + bl[1];
    }
}

// ---------------- host orchestration ----------------
template<int n>
static void run_bn(const float* Y, float* scratch, const float* Gw,
                   float* part, float* M0, float* M0s, float* M0is,
                   float* Lm, float* Gis, float* Ws, float* P) {
    k_psum<n><<<128, 256>>>(Y, part);
    k_mean_sym<n><<<1, 1024>>>(part, M0, 1.0f / NSAMP);
    k_meig<n><<<1, 1024>>>(M0, M0s, M0is);
    k_bn_log<n><<<NSAMP, 256>>>(Y, M0is, scratch);
    k_psum<n><<<128, 256>>>(scratch, part);
    k_mean_sym<n><<<1, 1024>>>(part, Lm, 1.0f / NSAMP);
    k_bn_stats<n><<<2, 1024>>>(Lm, M0s, Gw, Gis, Ws);
    k_pmul<n><<<1, 256>>>(Ws, Gis, P);
}

extern "C" void kernel_launch(void* const* d_in, const int* in_sizes, int n_in,
                              void* d_out, int out_size) {
    const float* x  = (const float*)d_in[0];
    const float* W1 = (const float*)d_in[1];
    const float* W2 = (const float*)d_in[2];
    const float* W3 = (const float*)d_in[3];
    const float* G1 = (const float*)d_in[4];
    const float* G2 = (const float*)d_in[5];
    const float* G3 = (const float*)d_in[6];
    const float* Wl = (const float*)d_in[7];
    const float* bl = (const float*)d_in[8];
    float* out = (float*)d_out;

    float *bufA, *bufB, *part, *M0, *M0s, *M0is, *Lm, *Gis, *Ws, *P;
    cudaGetSymbolAddress((void**)&bufA, g_bufA);
    cudaGetSymbolAddress((void**)&bufB, g_bufB);
    cudaGetSymbolAddress((void**)&part, g_part);
    cudaGetSymbolAddress((void**)&M0,   g_M0);
    cudaGetSymbolAddress((void**)&M0s,  g_M0s);
    cudaGetSymbolAddress((void**)&M0is, g_M0is);
    cudaGetSymbolAddress((void**)&Lm,   g_Lm);
    cudaGetSymbolAddress((void**)&Gis,  g_Gis);
    cudaGetSymbolAddress((void**)&Ws,   g_Ws);
    cudaGetSymbolAddress((void**)&P,    g_P);

    const int YE = NSAMP * 2;
    const int FE = NSAMP * 50 * 50;
    float* yout = nullptr;
    float* fout = nullptr;
    if (out_size >= YE + FE)      { yout = out; fout = out + YE; }
    else if (out_size == FE)      { fout = out; }
    else                          { yout = out; }

    // Layer 1: 62 -> 58
    k_bimap<62, 58><<<NSAMP, 256>>>(x, W1, bufA);
    run_bn<58>(bufA, bufB, G1, part, M0, M0s, M0is, Lm, Gis, Ws, P);
    k_bn_out<58><<<NSAMP, 256>>>(bufA, P, bufB);

    // Layer 2: 58 -> 54
    k_bimap<58, 54><<<NSAMP, 256>>>(bufB, W2, bufA);
    run_bn<54>(bufA, bufB, G2, part, M0, M0s, M0is, Lm, Gis, Ws, P);
    k_bn_out<54><<<NSAMP, 256>>>(bufA, P, bufB);

    // Layer 3: 54 -> 50 (no ReEig; LogEig + linear head)
    k_bimap<54, 50><<<NSAMP, 256>>>(bufB, W3, bufA);
    run_bn<50>(bufA, bufB, G3, part, M0, M0s, M0is, Lm, Gis, Ws, P);
    k_final<50><<<NSAMP, 256>>>(bufA, P, Wl, bl, fout, yout);
}